// round 14
// baseline (speedup 1.0000x reference)
#include <cuda_runtime.h>
#include <cuda_bf16.h>

#define NCTA 512
#define NT 128
#define TT 1024
#define BB 128
#define HH 256
#define GSZ 64   // CTAs per row-group

__device__ float g_h[2][BB * HH];
__device__ float g_u[BB * HH];
__device__ unsigned g_flags[8][GSZ][8];

__device__ __forceinline__ float4 ldcg4(const float4* p) {
    float4 v;
    asm volatile("ld.global.cg.v4.f32 {%0,%1,%2,%3}, [%4];"
                 : "=f"(v.x), "=f"(v.y), "=f"(v.z), "=f"(v.w) : "l"(p));
    return v;
}
__device__ __forceinline__ unsigned ldrelax(const unsigned* p) {
    unsigned v;
    asm volatile("ld.relaxed.gpu.global.u32 %0, [%1];" : "=r"(v) : "l"(p) : "memory");
    return v;
}
__device__ __forceinline__ float fast_tanh(float x) {
    float ax = fabsf(x);
    float e = __expf(2.0f * ax);
    float r = 1.0f - 2.0f / (e + 1.0f);
    return copysignf(r, x);
}
__device__ __forceinline__ float fast_sigmoid(float x) {
    return 1.0f / (1.0f + __expf(-x));
}

// Row-group barrier over 64 CTAs: own-flag store + 2-flags-per-lane poll.
__device__ __forceinline__ void group_bar(unsigned* fl, int nj, unsigned base, unsigned ep) {
    __syncthreads();
    if (threadIdx.x < 32) {
        if (threadIdx.x == 0) {
            asm volatile("fence.acq_rel.gpu;" ::: "memory");
            asm volatile("st.relaxed.gpu.global.u32 [%0], %1;"
                         :: "l"(fl + nj * 8), "r"(base + ep) : "memory");
        }
        unsigned v1, v2;
        unsigned* p1 = fl + threadIdx.x * 8;
        unsigned* p2 = fl + (threadIdx.x + 32) * 8;
        do { v1 = ldrelax(p1); v2 = ldrelax(p2); }
        while (__any_sync(0xffffffffu, ((v1 - base) < ep) || ((v2 - base) < ep)));
        asm volatile("fence.acq_rel.gpu;" ::: "memory");
    }
    __syncthreads();
}

// SMEM layout (floats), total 13826 floats = 55,304 B  (x4 CTAs ~ 221KB/SM)
#define OFF_W1S 0                     // [256][20]
#define OFF_W2S 5120                  // [256][8]
#define OFF_TILE 7168                 // [64][16][4]  shared h/u staging
#define OFF_S1  11264                 // [4][20][17]
#define OFF_S2  12624                 // [4][8][17]
#define OFF_HOLD 13168                // [64]
#define OFF_AMP 13232                 // [16]
#define OFF_COS 13248
#define OFF_SIN 13264
#define OFF_W0  13280                 // [3][4]
#define OFF_B1  13292                 // [3][4]
#define OFF_BZ  13304                 // [4]
#define OFF_BH  13308                 // [4]
#define OFF_WOF 13312                 // [256][2]
#define OFF_BO  13824                 // [2]
#define SMEM_FLOATS 13826
#define SMEM_BYTES (SMEM_FLOATS * 4)

__global__ void __launch_bounds__(NT, 4) pgjanet_kernel(
    const float* __restrict__ x,   const float* __restrict__ h0,
    const float* __restrict__ Wa,  const float* __restrict__ ba,
    const float* __restrict__ Wp1, const float* __restrict__ bp1,
    const float* __restrict__ Wp2, const float* __restrict__ bp2,
    const float* __restrict__ Wz,  const float* __restrict__ bz,
    const float* __restrict__ Wh,  const float* __restrict__ bh,
    const float* __restrict__ Wo,  const float* __restrict__ bo,
    float* __restrict__ out)
{
    extern __shared__ float sm[];
    float* W1s = sm + OFF_W1S;
    float* W2s = sm + OFF_W2S;
    float* tile = sm + OFF_TILE;
    float* S1  = sm + OFF_S1;
    float* S2  = sm + OFF_S2;
    float* s_hold = sm + OFF_HOLD;
    float* s_amp = sm + OFF_AMP;
    float* s_cos = sm + OFF_COS;
    float* s_sin = sm + OFF_SIN;
    float* s_w0  = sm + OFF_W0;
    float* s_b1  = sm + OFF_B1;
    float* s_bz  = sm + OFF_BZ;
    float* s_bh  = sm + OFF_BH;
    float* s_Wo  = sm + OFF_WOF;
    float* s_bo  = sm + OFF_BO;

    const int tid  = threadIdx.x;
    const int lane = tid & 31;
    const int wid  = tid >> 5;
    const int nj = blockIdx.x & 63;   // column slice (4 cols)
    const int mi = blockIdx.x >> 6;   // row group (16 rows), 8 groups
    const int j0 = nj * 4;
    const int r0 = mi * 16;

    unsigned* fl = &g_flags[mi][0][0];

    unsigned base = 0;
    if (tid < 32)
        base = ldrelax(fl + nj * 8);   // own flag (all lanes same addr)

    // ---- preload loop-invariant weights ----
    for (int idx = tid; idx < 256 * 20; idx += NT) {
        int k = idx / 20, nn = idx % 20;
        int mat = nn >> 2, j = j0 + (nn & 3);
        float v;
        if      (mat == 0) v = Wa [(1 + k) * HH + j];
        else if (mat == 1) v = Wp1[(1 + k) * HH + j];
        else if (mat == 2) v = Wp2[(1 + k) * HH + j];
        else if (mat == 3) v = Wz [(HH + k) * HH + j];
        else               v = Wh [(HH + k) * HH + j];
        W1s[k * 20 + nn] = v;
    }
    for (int idx = tid; idx < 256 * 8; idx += NT) {
        int k = idx >> 3, nn = idx & 7;
        int j = j0 + (nn & 3);
        W2s[k * 8 + nn] = (nn < 4) ? Wz[k * HH + j] : Wh[k * HH + j];
    }
    for (int idx = tid; idx < 512; idx += NT) s_Wo[idx] = Wo[idx];
    if (tid < 4) {
        int j = j0 + tid;
        s_w0[tid]     = Wa [j];  s_w0[4 + tid] = Wp1[j];  s_w0[8 + tid] = Wp2[j];
        s_b1[tid]     = ba [j];  s_b1[4 + tid] = bp1[j];  s_b1[8 + tid] = bp2[j];
        s_bz[tid] = bz[j];       s_bh[tid] = bh[j];
    }
    if (tid == 0) { s_bo[0] = bo[0]; s_bo[1] = bo[1]; }

    unsigned ep = 0;

    for (int t = 0; t < TT; ++t) {
        // ---- stage 1: load h(t_in) tile [64 kc][16 r][4] ----
        const float* hsrc = (t == 0) ? h0 : g_h[t & 1];
        for (int idx = tid; idx < 16 * 64; idx += NT) {
            int r = idx >> 6, kc = idx & 63;
            float4 v = ldcg4((const float4*)(hsrc + (r0 + r) * HH) + kc);
            *(float4*)&tile[(kc * 16 + r) * 4] = v;
        }
        if (tid < 16) {
            const float* xp = x + (((r0 + tid) * TT) + t) * 2;
            float amp = __ldg(xp), ph = __ldg(xp + 1);
            s_amp[tid] = amp;
            float sv, cv; sincosf(ph, &sv, &cv);
            s_sin[tid] = sv; s_cos[tid] = cv;
        }
        __syncthreads();

        // ---- GEMM1: 4 warps, each full 20 cols x k-quarter (sub -> eighth) ----
        {
            int r = lane & 15, sub = lane >> 4;
            int ke8 = wid * 2 + sub;          // k-eighth, 8 kc each
            float acc[20];
            #pragma unroll
            for (int c = 0; c < 20; ++c) acc[c] = 0.f;
            #pragma unroll
            for (int mm = 0; mm < 8; ++mm) {
                int kc = ke8 * 8 + mm;
                float4 hv = *(const float4*)&tile[(kc * 16 + r) * 4];
                #pragma unroll
                for (int d = 0; d < 4; ++d) {
                    float hk = (d == 0) ? hv.x : (d == 1) ? hv.y : (d == 2) ? hv.z : hv.w;
                    const float* wrow = W1s + (kc * 4 + d) * 20;
                    #pragma unroll
                    for (int c4 = 0; c4 < 5; ++c4) {
                        float4 w = *(const float4*)&wrow[c4 * 4];
                        acc[c4 * 4 + 0] += hk * w.x;
                        acc[c4 * 4 + 1] += hk * w.y;
                        acc[c4 * 4 + 2] += hk * w.z;
                        acc[c4 * 4 + 3] += hk * w.w;
                    }
                }
            }
            #pragma unroll
            for (int c = 0; c < 20; ++c)
                acc[c] += __shfl_down_sync(0xffffffffu, acc[c], 16);
            if (sub == 0) {
                float* s = S1 + wid * 340;
                #pragma unroll
                for (int c = 0; c < 20; ++c) s[c * 17 + r] = acc[c];
            }
        }
        __syncthreads();

        // ---- epilogue 1 (tid<64): a,p1,p2 -> u ; stash hold ----
        if (tid < 64) {
            int jj = tid & 3, r = tid >> 2;
            float sa = 0.f, sp1 = 0.f, sp2 = 0.f;
            #pragma unroll
            for (int q = 0; q < 4; ++q) {
                sa  += S1[q * 340 + (0 + jj) * 17 + r];
                sp1 += S1[q * 340 + (4 + jj) * 17 + r];
                sp2 += S1[q * 340 + (8 + jj) * 17 + r];
            }
            float a  = fast_tanh(sa  + s_amp[r] * s_w0[jj]     + s_b1[jj]);
            float p1 = fast_tanh(sp1 + s_cos[r] * s_w0[4 + jj] + s_b1[4 + jj]);
            float p2 = fast_tanh(sp2 + s_sin[r] * s_w0[8 + jj] + s_b1[8 + jj]);
            g_u[(r0 + r) * HH + j0 + jj] =
                a * p1 * p2 * (1.f - a) * (1.f - p1) * (1.f - p2);
            int j = j0 + jj;
            s_hold[tid] = tile[((j >> 2) * 16 + r) * 4 + (j & 3)];
        }
        group_bar(fl, nj, base, ++ep);

        // ---- stage 2: load u tile (reuses the same buffer) ----
        for (int idx = tid; idx < 16 * 64; idx += NT) {
            int r = idx >> 6, kc = idx & 63;
            float4 v = ldcg4((const float4*)(g_u + (r0 + r) * HH) + kc);
            *(float4*)&tile[(kc * 16 + r) * 4] = v;
        }
        __syncthreads();

        // ---- GEMM2: 4 warps, each full 8 cols x k-quarter (sub -> eighth) ----
        {
            int r = lane & 15, sub = lane >> 4;
            int ke8 = wid * 2 + sub;
            float acc[8];
            #pragma unroll
            for (int c = 0; c < 8; ++c) acc[c] = 0.f;
            #pragma unroll
            for (int mm = 0; mm < 8; ++mm) {
                int kc = ke8 * 8 + mm;
                float4 uv = *(const float4*)&tile[(kc * 16 + r) * 4];
                #pragma unroll
                for (int d = 0; d < 4; ++d) {
                    float uk = (d == 0) ? uv.x : (d == 1) ? uv.y : (d == 2) ? uv.z : uv.w;
                    const float* wrow = W2s + (kc * 4 + d) * 8;
                    float4 w0 = *(const float4*)&wrow[0];
                    float4 w1 = *(const float4*)&wrow[4];
                    acc[0] += uk * w0.x; acc[1] += uk * w0.y;
                    acc[2] += uk * w0.z; acc[3] += uk * w0.w;
                    acc[4] += uk * w1.x; acc[5] += uk * w1.y;
                    acc[6] += uk * w1.z; acc[7] += uk * w1.w;
                }
            }
            #pragma unroll
            for (int c = 0; c < 8; ++c)
                acc[c] += __shfl_down_sync(0xffffffffu, acc[c], 16);
            if (sub == 0) {
                float* s = S2 + wid * 136;
                #pragma unroll
                for (int c = 0; c < 8; ++c) s[c * 17 + r] = acc[c];
            }
        }
        __syncthreads();

        // ---- epilogue 2 (tid<64) + out-projection (tid>=64, nj==0) ----
        if (tid < 64) {
            int jj = tid & 3, r = tid >> 2;
            int j = j0 + jj;
            float zp = s_bz[jj], hp = s_bh[jj];
            #pragma unroll
            for (int q = 0; q < 4; ++q) {
                zp += S2[q * 136 + jj * 17 + r];
                hp += S2[q * 136 + (4 + jj) * 17 + r];
                zp += S1[q * 340 + (12 + jj) * 17 + r];
                hp += S1[q * 340 + (16 + jj) * 17 + r];
            }
            float z  = fast_sigmoid(zp);
            float hc = fast_tanh(hp);
            float hn = z * s_hold[tid] + (1.f - z) * hc;
            g_h[(t + 1) & 1][(r0 + r) * HH + j] = hn;
            if (t == TT - 1)
                out[BB * TT * 2 + (r0 + r) * HH + j] = hn;
        } else if (nj == 0 && t >= 1) {
            // out row t-1 from g_h[t&1] (= h_out(t-1), stable this step)
            const float* hb = g_h[t & 1];
            #pragma unroll
            for (int it2 = 0; it2 < 2; ++it2) {
                int item = (tid - 64) + it2 * 64;
                int r = item >> 3, kk = item & 7;
                float o0 = 0.f, o1 = 0.f;
                #pragma unroll
                for (int q = 0; q < 8; ++q) {
                    float4 hv = ldcg4((const float4*)(hb + (r0 + r) * HH + kk * 32) + q);
                    int k = kk * 32 + q * 4;
                    o0 += hv.x * s_Wo[k * 2]     + hv.y * s_Wo[k * 2 + 2]
                        + hv.z * s_Wo[k * 2 + 4] + hv.w * s_Wo[k * 2 + 6];
                    o1 += hv.x * s_Wo[k * 2 + 1] + hv.y * s_Wo[k * 2 + 3]
                        + hv.z * s_Wo[k * 2 + 5] + hv.w * s_Wo[k * 2 + 7];
                }
                o0 += __shfl_xor_sync(0xffffffffu, o0, 1);
                o0 += __shfl_xor_sync(0xffffffffu, o0, 2);
                o0 += __shfl_xor_sync(0xffffffffu, o0, 4);
                o1 += __shfl_xor_sync(0xffffffffu, o1, 1);
                o1 += __shfl_xor_sync(0xffffffffu, o1, 2);
                o1 += __shfl_xor_sync(0xffffffffu, o1, 4);
                if (kk == 0) {
                    float* op = out + (((r0 + r) * TT) + (t - 1)) * 2;
                    op[0] = o0 + s_bo[0];
                    op[1] = o1 + s_bo[1];
                }
            }
        }
        group_bar(fl, nj, base, ++ep);
    }

    // ---- final output row t=1023 from g_h[0] (= h_out(1023)) ----
    if (nj == 0 && tid < 128) {
        int r = tid >> 3, kk = tid & 7;
        const float* hb = g_h[TT & 1];
        float o0 = 0.f, o1 = 0.f;
        #pragma unroll
        for (int q = 0; q < 8; ++q) {
            float4 hv = ldcg4((const float4*)(hb + (r0 + r) * HH + kk * 32) + q);
            int k = kk * 32 + q * 4;
            o0 += hv.x * s_Wo[k * 2]     + hv.y * s_Wo[k * 2 + 2]
                + hv.z * s_Wo[k * 2 + 4] + hv.w * s_Wo[k * 2 + 6];
            o1 += hv.x * s_Wo[k * 2 + 1] + hv.y * s_Wo[k * 2 + 3]
                + hv.z * s_Wo[k * 2 + 5] + hv.w * s_Wo[k * 2 + 7];
        }
        o0 += __shfl_xor_sync(0xffffffffu, o0, 1);
        o0 += __shfl_xor_sync(0xffffffffu, o0, 2);
        o0 += __shfl_xor_sync(0xffffffffu, o0, 4);
        o1 += __shfl_xor_sync(0xffffffffu, o1, 1);
        o1 += __shfl_xor_sync(0xffffffffu, o1, 2);
        o1 += __shfl_xor_sync(0xffffffffu, o1, 4);
        if (kk == 0) {
            float* op = out + (((r0 + r) * TT) + (TT - 1)) * 2;
            op[0] = o0 + s_bo[0];
            op[1] = o1 + s_bo[1];
        }
    }
}

extern "C" void kernel_launch(void* const* d_in, const int* in_sizes, int n_in,
                              void* d_out, int out_size) {
    const float* x   = (const float*)d_in[0];
    const float* h0  = (const float*)d_in[1];
    const float* Wa  = (const float*)d_in[2];
    const float* ba  = (const float*)d_in[3];
    const float* Wp1 = (const float*)d_in[4];
    const float* bp1 = (const float*)d_in[5];
    const float* Wp2 = (const float*)d_in[6];
    const float* bp2 = (const float*)d_in[7];
    const float* Wz  = (const float*)d_in[8];
    const float* bz  = (const float*)d_in[9];
    const float* Wh  = (const float*)d_in[10];
    const float* bh  = (const float*)d_in[11];
    const float* Wo  = (const float*)d_in[12];
    const float* bo  = (const float*)d_in[13];
    float* out = (float*)d_out;

    cudaFuncSetAttribute(pgjanet_kernel,
                         cudaFuncAttributeMaxDynamicSharedMemorySize, SMEM_BYTES);
    pgjanet_kernel<<<NCTA, NT, SMEM_BYTES>>>(
        x, h0, Wa, ba, Wp1, bp1, Wp2, bp2, Wz, bz, Wh, bh, Wo, bo, out);
}

// round 16
// speedup vs baseline: 1.1043x; 1.1043x over previous
#include <cuda_runtime.h>
#include <cuda_bf16.h>

#define NCTA 256
#define NT 320
#define TT 1024
#define BB 128
#define HH 256

__device__ float g_h[BB * HH];
__device__ float g_u[BB * HH];
__device__ unsigned g_flags[8][32][8];

__device__ __forceinline__ float4 ldcg4(const float4* p) {
    float4 v;
    asm volatile("ld.global.cg.v4.f32 {%0,%1,%2,%3}, [%4];"
                 : "=f"(v.x), "=f"(v.y), "=f"(v.z), "=f"(v.w) : "l"(p));
    return v;
}
__device__ __forceinline__ float ldcg1(const float* p) {
    float v;
    asm volatile("ld.global.cg.f32 %0, [%1];" : "=f"(v) : "l"(p));
    return v;
}
__device__ __forceinline__ unsigned ldrelax(const unsigned* p) {
    unsigned v;
    asm volatile("ld.relaxed.gpu.global.u32 %0, [%1];" : "=r"(v) : "l"(p) : "memory");
    return v;
}
__device__ __forceinline__ float fast_tanh(float x) {
    float ax = fabsf(x);
    float e = __expf(2.0f * ax);
    float r = 1.0f - 2.0f / (e + 1.0f);
    return copysignf(r, x);
}
__device__ __forceinline__ float fast_sigmoid(float x) {
    return 1.0f / (1.0f + __expf(-x));
}

// Row-group barrier: 32 CTAs (same mi), flag store + 32-lane poll in warp 0.
__device__ __forceinline__ void group_bar(unsigned* fl, int nj, unsigned base, unsigned ep) {
    __syncthreads();
    if (threadIdx.x < 32) {
        if (threadIdx.x == 0) {
            asm volatile("fence.acq_rel.gpu;" ::: "memory");
            asm volatile("st.relaxed.gpu.global.u32 [%0], %1;"
                         :: "l"(fl + nj * 8), "r"(base + ep) : "memory");
        }
        unsigned v;
        unsigned* p = fl + threadIdx.x * 8;
        do { v = ldrelax(p); }
        while (__any_sync(0xffffffffu, (v - base) < ep));
        asm volatile("fence.acq_rel.gpu;" ::: "memory");
    }
    __syncthreads();
}

// SMEM layout (floats). Weight rows padded to 44 / 20 (multiples of 4: keeps
// float4 alignment) so the two lane-half k-subs (adjacent kc, delta = 4*stride
// = 16 mod 32 banks) broadcast conflict-free.
#define OFF_W1S 0                     // [256][44]
#define OFF_W2S 11264                 // [256][20]
#define OFF_H4S 16384                 // [64][16][4]
#define OFF_U4S 20480                 // [64][16][4]
#define OFF_S1  24576                 // [2][40][17]
#define OFF_S2  25936                 // [4][16][17]
#define OFF_AMP 27024                 // [16]
#define OFF_COS 27040
#define OFF_SIN 27056
#define OFF_W0  27072                 // [3][8]
#define OFF_B1  27096                 // [3][8]
#define OFF_BZ  27120                 // [8]
#define OFF_BH  27128                 // [8]
#define OFF_WOF 27136                 // [256][2]
#define OFF_BO  27648                 // [2]
#define SMEM_FLOATS 27650
#define SMEM_BYTES (SMEM_FLOATS * 4)

__global__ void __launch_bounds__(NT, 2) pgjanet_kernel(
    const float* __restrict__ x,   const float* __restrict__ h0,
    const float* __restrict__ Wa,  const float* __restrict__ ba,
    const float* __restrict__ Wp1, const float* __restrict__ bp1,
    const float* __restrict__ Wp2, const float* __restrict__ bp2,
    const float* __restrict__ Wz,  const float* __restrict__ bz,
    const float* __restrict__ Wh,  const float* __restrict__ bh,
    const float* __restrict__ Wo,  const float* __restrict__ bo,
    float* __restrict__ out)
{
    extern __shared__ float sm[];
    float* W1s = sm + OFF_W1S;
    float* W2s = sm + OFF_W2S;
    float* h4s = sm + OFF_H4S;
    float* u4s = sm + OFF_U4S;
    float* S1  = sm + OFF_S1;
    float* S2  = sm + OFF_S2;
    float* s_amp = sm + OFF_AMP;
    float* s_cos = sm + OFF_COS;
    float* s_sin = sm + OFF_SIN;
    float* s_w0  = sm + OFF_W0;
    float* s_b1  = sm + OFF_B1;
    float* s_bz  = sm + OFF_BZ;
    float* s_bh  = sm + OFF_BH;
    float* s_Wo  = sm + OFF_WOF;
    float* s_bo  = sm + OFF_BO;

    const int tid  = threadIdx.x;
    const int lane = tid & 31;
    const int wid  = tid >> 5;
    const int nj = blockIdx.x & 31;   // column slice (8 cols)
    const int mi = blockIdx.x >> 5;   // row group (16 rows), 8 groups
    const int j0 = nj * 8;
    const int r0 = mi * 16;

    unsigned* fl = &g_flags[mi][0][0];

    unsigned base = 0;
    if (tid < 32)
        base = ldrelax(fl + nj * 8);   // own flag; only warp 0 uses base

    // ---- preload loop-invariant weights into SMEM (padded strides) ----
    for (int idx = tid; idx < 256 * 40; idx += NT) {
        int k = idx / 40, nn = idx % 40;
        int mat = nn >> 3, j = j0 + (nn & 7);
        float v;
        if      (mat == 0) v = Wa [(1 + k) * HH + j];
        else if (mat == 1) v = Wp1[(1 + k) * HH + j];
        else if (mat == 2) v = Wp2[(1 + k) * HH + j];
        else if (mat == 3) v = Wz [(HH + k) * HH + j];
        else               v = Wh [(HH + k) * HH + j];
        W1s[k * 44 + nn] = v;
    }
    for (int idx = tid; idx < 256 * 16; idx += NT) {
        int k = idx / 16, nn = idx % 16;
        int j = j0 + (nn & 7);
        W2s[k * 20 + nn] = (nn < 8) ? Wz[k * HH + j] : Wh[k * HH + j];
    }
    for (int idx = tid; idx < 512; idx += NT) s_Wo[idx] = Wo[idx];
    if (tid < 8) {
        int j = j0 + tid;
        s_w0[tid]      = Wa [j];  s_w0[8 + tid]  = Wp1[j];  s_w0[16 + tid] = Wp2[j];
        s_b1[tid]      = ba [j];  s_b1[8 + tid]  = bp1[j];  s_b1[16 + tid] = bp2[j];
        s_bz[tid] = bz[j];        s_bh[tid] = bh[j];
    }
    if (tid == 0) { s_bo[0] = bo[0]; s_bo[1] = bo[1]; }

    unsigned ep = 0;

    for (int t = 0; t < TT; ++t) {
        // ---- stage 1: load 16-row h tile into SMEM ([kc][row][4]) ----
        const float* hsrc = (t == 0) ? h0 : g_h;
        for (int idx = tid; idx < 16 * 64; idx += NT) {
            int r = idx >> 6, kc = idx & 63;
            float4 v = ldcg4((const float4*)(hsrc + (r0 + r) * HH) + kc);
            *(float4*)&h4s[(kc * 16 + r) * 4] = v;
        }
        if (tid < 16) {
            const float* xp = x + (((r0 + tid) * TT) + t) * 2;
            float amp = __ldg(xp), ph = __ldg(xp + 1);
            s_amp[tid] = amp;
            float sv, cv; sincosf(ph, &sv, &cv);
            s_sin[tid] = sv; s_cos[tid] = cv;
        }
        __syncthreads();

        // ---- GEMM1: 10 warps = 5 cg (8 cols) x 2 kh; subs interleave kc ----
        {
            int cg = wid % 5, kh = wid / 5;
            int r = lane & 15, sub = lane >> 4;
            float a0 = 0.f, a1 = 0.f, a2 = 0.f, a3 = 0.f;
            float a4 = 0.f, a5 = 0.f, a6 = 0.f, a7 = 0.f;
            const float* wp = W1s + cg * 8;
            #pragma unroll 4
            for (int mm = 0; mm < 16; ++mm) {
                int m = kh * 32 + mm * 2 + sub;   // adjacent-kc interleave
                float4 hv = *(const float4*)&h4s[(m * 16 + r) * 4];
                #pragma unroll
                for (int d = 0; d < 4; ++d) {
                    float hk = (d == 0) ? hv.x : (d == 1) ? hv.y : (d == 2) ? hv.z : hv.w;
                    float4 w0 = *(const float4*)&wp[(4 * m + d) * 44];
                    float4 w1 = *(const float4*)&wp[(4 * m + d) * 44 + 4];
                    a0 += hk * w0.x; a1 += hk * w0.y; a2 += hk * w0.z; a3 += hk * w0.w;
                    a4 += hk * w1.x; a5 += hk * w1.y; a6 += hk * w1.z; a7 += hk * w1.w;
                }
            }
            a0 += __shfl_down_sync(0xffffffffu, a0, 16);
            a1 += __shfl_down_sync(0xffffffffu, a1, 16);
            a2 += __shfl_down_sync(0xffffffffu, a2, 16);
            a3 += __shfl_down_sync(0xffffffffu, a3, 16);
            a4 += __shfl_down_sync(0xffffffffu, a4, 16);
            a5 += __shfl_down_sync(0xffffffffu, a5, 16);
            a6 += __shfl_down_sync(0xffffffffu, a6, 16);
            a7 += __shfl_down_sync(0xffffffffu, a7, 16);
            if (sub == 0) {
                float* s = S1 + kh * 680 + (cg * 8) * 17 + r;
                s[0]   = a0; s[17]  = a1; s[34]  = a2; s[51]  = a3;
                s[68]  = a4; s[85]  = a5; s[102] = a6; s[119] = a7;
            }
        }
        __syncthreads();

        // ---- epilogue 1: a, p1, p2 -> u (128 threads: 16 rows x 8 cols) ----
        if (tid < 128) {
            int jj = tid & 7, r = tid >> 3;
            float sa  = S1[(0  + jj) * 17 + r] + S1[680 + (0  + jj) * 17 + r];
            float sp1 = S1[(8  + jj) * 17 + r] + S1[680 + (8  + jj) * 17 + r];
            float sp2 = S1[(16 + jj) * 17 + r] + S1[680 + (16 + jj) * 17 + r];
            float a  = fast_tanh(sa  + s_amp[r] * s_w0[jj]      + s_b1[jj]);
            float p1 = fast_tanh(sp1 + s_cos[r] * s_w0[8 + jj]  + s_b1[8 + jj]);
            float p2 = fast_tanh(sp2 + s_sin[r] * s_w0[16 + jj] + s_b1[16 + jj]);
            g_u[(r0 + r) * HH + j0 + jj] =
                a * p1 * p2 * (1.f - a) * (1.f - p1) * (1.f - p2);
        }
        group_bar(fl, nj, base, ++ep);

        // ---- stage 2: load u tile ----
        for (int idx = tid; idx < 16 * 64; idx += NT) {
            int r = idx >> 6, kc = idx & 63;
            float4 v = ldcg4((const float4*)(g_u + (r0 + r) * HH) + kc);
            *(float4*)&u4s[(kc * 16 + r) * 4] = v;
        }
        __syncthreads();

        // ---- GEMM2: warps 0-7 = 2 cg2 (8 cols) x 4 ke; subs interleave kc ----
        if (wid < 8) {
            int cg2 = wid & 1, ke = wid >> 1;
            int r = lane & 15, sub = lane >> 4;
            float a0 = 0.f, a1 = 0.f, a2 = 0.f, a3 = 0.f;
            float a4 = 0.f, a5 = 0.f, a6 = 0.f, a7 = 0.f;
            const float* wp = W2s + cg2 * 8;
            #pragma unroll 4
            for (int mm = 0; mm < 8; ++mm) {
                int m = ke * 16 + mm * 2 + sub;   // adjacent-kc interleave
                float4 uv = *(const float4*)&u4s[(m * 16 + r) * 4];
                #pragma unroll
                for (int d = 0; d < 4; ++d) {
                    float uk = (d == 0) ? uv.x : (d == 1) ? uv.y : (d == 2) ? uv.z : uv.w;
                    float4 w0 = *(const float4*)&wp[(4 * m + d) * 20];
                    float4 w1 = *(const float4*)&wp[(4 * m + d) * 20 + 4];
                    a0 += uk * w0.x; a1 += uk * w0.y; a2 += uk * w0.z; a3 += uk * w0.w;
                    a4 += uk * w1.x; a5 += uk * w1.y; a6 += uk * w1.z; a7 += uk * w1.w;
                }
            }
            a0 += __shfl_down_sync(0xffffffffu, a0, 16);
            a1 += __shfl_down_sync(0xffffffffu, a1, 16);
            a2 += __shfl_down_sync(0xffffffffu, a2, 16);
            a3 += __shfl_down_sync(0xffffffffu, a3, 16);
            a4 += __shfl_down_sync(0xffffffffu, a4, 16);
            a5 += __shfl_down_sync(0xffffffffu, a5, 16);
            a6 += __shfl_down_sync(0xffffffffu, a6, 16);
            a7 += __shfl_down_sync(0xffffffffu, a7, 16);
            if (sub == 0) {
                float* s = S2 + ke * 272 + (cg2 * 8) * 17 + r;
                s[0]   = a0; s[17]  = a1; s[34]  = a2; s[51]  = a3;
                s[68]  = a4; s[85]  = a5; s[102] = a6; s[119] = a7;
            }
        } else if (nj == 0 && t >= 1) {
            // warps 8,9: output row t-1 from h4s (= h(t-1)), 16 rows
            #pragma unroll
            for (int it = 0; it < 2; ++it) {
                int item = it * 64 + (wid - 8) * 32 + lane;   // 0..127
                int r = item >> 3, kk = item & 7;
                float o0 = 0.f, o1 = 0.f;
                for (int k = kk * 32; k < kk * 32 + 32; ++k) {
                    float v = h4s[(k >> 2) * 64 + r * 4 + (k & 3)];
                    o0 += v * s_Wo[k * 2];
                    o1 += v * s_Wo[k * 2 + 1];
                }
                o0 += __shfl_xor_sync(0xffffffffu, o0, 1);
                o0 += __shfl_xor_sync(0xffffffffu, o0, 2);
                o0 += __shfl_xor_sync(0xffffffffu, o0, 4);
                o1 += __shfl_xor_sync(0xffffffffu, o1, 1);
                o1 += __shfl_xor_sync(0xffffffffu, o1, 2);
                o1 += __shfl_xor_sync(0xffffffffu, o1, 4);
                if (kk == 0) {
                    float* op = out + (((r0 + r) * TT) + (t - 1)) * 2;
                    op[0] = o0 + s_bo[0];
                    op[1] = o1 + s_bo[1];
                }
            }
        }
        __syncthreads();

        // ---- epilogue 2: z, h_cand, h_new (128 threads) ----
        if (tid < 128) {
            int jj = tid & 7, r = tid >> 3;
            int j = j0 + jj;
            float zp = s_bz[jj], hp = s_bh[jj];
            #pragma unroll
            for (int e = 0; e < 4; ++e) {
                zp += S2[e * 272 + jj * 17 + r];
                hp += S2[e * 272 + (8 + jj) * 17 + r];
            }
            zp += S1[(24 + jj) * 17 + r] + S1[680 + (24 + jj) * 17 + r];
            hp += S1[(32 + jj) * 17 + r] + S1[680 + (32 + jj) * 17 + r];
            float z  = fast_sigmoid(zp);
            float hc = fast_tanh(hp);
            float hold = h4s[(j >> 2) * 64 + r * 4 + (j & 3)];
            float hn = z * hold + (1.f - z) * hc;
            g_h[(r0 + r) * HH + j] = hn;
            if (t == TT - 1)
                out[BB * TT * 2 + (r0 + r) * HH + j] = hn;
        }
        group_bar(fl, nj, base, ++ep);
    }

    // ---- final output row t=1023 from g_h (after final barrier) ----
    if (nj == 0 && tid < 128) {
        int r = tid >> 3, kk = tid & 7;
        float o0 = 0.f, o1 = 0.f;
        for (int k = kk * 32; k < kk * 32 + 32; ++k) {
            float v = ldcg1(&g_h[(r0 + r) * HH + k]);
            o0 += v * s_Wo[k * 2];
            o1 += v * s_Wo[k * 2 + 1];
        }
        o0 += __shfl_xor_sync(0xffffffffu, o0, 1);
        o0 += __shfl_xor_sync(0xffffffffu, o0, 2);
        o0 += __shfl_xor_sync(0xffffffffu, o0, 4);
        o1 += __shfl_xor_sync(0xffffffffu, o1, 1);
        o1 += __shfl_xor_sync(0xffffffffu, o1, 2);
        o1 += __shfl_xor_sync(0xffffffffu, o1, 4);
        if (kk == 0) {
            float* op = out + (((r0 + r) * TT) + (TT - 1)) * 2;
            op[0] = o0 + s_bo[0];
            op[1] = o1 + s_bo[1];
        }
    }
}

extern "C" void kernel_launch(void* const* d_in, const int* in_sizes, int n_in,
                              void* d_out, int out_size) {
    const float* x   = (const float*)d_in[0];
    const float* h0  = (const float*)d_in[1];
    const float* Wa  = (const float*)d_in[2];
    const float* ba  = (const float*)d_in[3];
    const float* Wp1 = (const float*)d_in[4];
    const float* bp1 = (const float*)d_in[5];
    const float* Wp2 = (const float*)d_in[6];
    const float* bp2 = (const float*)d_in[7];
    const float* Wz  = (const float*)d_in[8];
    const float* bz  = (const float*)d_in[9];
    const float* Wh  = (const float*)d_in[10];
    const float* bh  = (const float*)d_in[11];
    const float* Wo  = (const float*)d_in[12];
    const float* bo  = (const float*)d_in[13];
    float* out = (float*)d_out;

    cudaFuncSetAttribute(pgjanet_kernel,
                         cudaFuncAttributeMaxDynamicSharedMemorySize, SMEM_BYTES);
    pgjanet_kernel<<<NCTA, NT, SMEM_BYTES>>>(
        x, h0, Wa, ba, Wp1, bp1, Wp2, bp2, Wz, bz, Wh, bh, Wo, bo, out);
}